// round 4
// baseline (speedup 1.0000x reference)
#include <cuda_runtime.h>
#include <math.h>
#include <stdint.h>

#define BB    64
#define DD    1024
#define LL    2048
#define DH    512
#define SPLIT 16
#define LC    (LL / SPLIT)   // 128 rows per CTA
#define NP    (LC / 8)       // 16 pairs per warp (4 warps, 2 rows each)

// ---------------- device scratch (explicitly 16B-aligned) ----------------
__device__ __align__(16) float g_target[BB * DD];
__device__ __align__(16) float g_acc5[BB * DD];
__device__ __align__(16) float g_wctx[BB * DD];
__device__ __align__(16) float g_pm[BB * 2 * SPLIT];
__device__ __align__(16) float g_ps[BB * 2 * SPLIT];
__device__ __align__(16) float g_pacc[BB * 2 * SPLIT * DH];
__device__ unsigned g_tile_ctr[16];

// ---------------- prep: zero accumulators + ticket counters ----------------
__global__ void prep_kernel() {
    int i = blockIdx.x * blockDim.x + threadIdx.x;
    if (i < BB * DD) { g_target[i] = 0.f; g_acc5[i] = 0.f; }
    if (i < 16) g_tile_ctr[i] = 0u;
}

// ---------------- split-K NT GEMM body (M=64, tiles 64x64, atomic epilogue) ----
__device__ __forceinline__ void gemm_body(const float* __restrict__ A, int lda,
                                          const float* __restrict__ B, int ldb,
                                          float* __restrict__ C, int kchunk) {
    __shared__ __align__(16) float As[16][68];
    __shared__ __align__(16) float Bs[16][68];
    int tid  = threadIdx.x;
    int tx   = tid & 15, ty = tid >> 4;
    int lrow = tid >> 2, lcol = (tid & 3) << 2;
    int n0   = blockIdx.x * 64;
    int k0   = blockIdx.y * kchunk;

    const float* Ap = A + (size_t)lrow * lda + lcol;
    const float* Bp = B + (size_t)(n0 + lrow) * ldb + lcol;

    float acc[4][4];
#pragma unroll
    for (int i = 0; i < 4; i++)
#pragma unroll
        for (int j = 0; j < 4; j++) acc[i][j] = 0.f;

    for (int kk = k0; kk < k0 + kchunk; kk += 16) {
        float4 a = *(const float4*)(Ap + kk);
        float4 b = *(const float4*)(Bp + kk);
        __syncthreads();
        As[lcol + 0][lrow] = a.x; As[lcol + 1][lrow] = a.y;
        As[lcol + 2][lrow] = a.z; As[lcol + 3][lrow] = a.w;
        Bs[lcol + 0][lrow] = b.x; Bs[lcol + 1][lrow] = b.y;
        Bs[lcol + 2][lrow] = b.z; Bs[lcol + 3][lrow] = b.w;
        __syncthreads();
#pragma unroll
        for (int k = 0; k < 16; k++) {
            float4 av = *(const float4*)&As[k][ty << 2];
            float4 bv = *(const float4*)&Bs[k][tx << 2];
            float aa[4] = {av.x, av.y, av.z, av.w};
            float bb[4] = {bv.x, bv.y, bv.z, bv.w};
#pragma unroll
            for (int i = 0; i < 4; i++)
#pragma unroll
                for (int j = 0; j < 4; j++)
                    acc[i][j] = fmaf(aa[i], bb[j], acc[i][j]);
        }
    }
    int row = ty << 2, col = n0 + (tx << 2);
#pragma unroll
    for (int i = 0; i < 4; i++)
#pragma unroll
        for (int j = 0; j < 4; j++)
            atomicAdd(&C[(size_t)(row + i) * DD + col + j], acc[i][j]);
}

// z=0: g_target += input @ W_in^T ; z=1: g_acc5 += input @ W_out[:,1024:2048]^T
__global__ __launch_bounds__(256) void gemm_dual(const float* __restrict__ inp,
                                                 const float* __restrict__ Win,
                                                 const float* __restrict__ Wout) {
    if (blockIdx.z == 0) gemm_body(inp, DD, Win, DD, g_target, DD / 8);
    else                 gemm_body(inp, DD, Wout + DD, 2 * DD, g_acc5, DD / 8);
}

// g_acc5 += g_wctx @ W_out[:,0:1024]^T ; last split-CTA per n-tile applies tanh
__global__ __launch_bounds__(256) void gemm_out_b(const float* __restrict__ Wout,
                                                  float* __restrict__ out) {
    gemm_body(g_wctx, DD, Wout, 2 * DD, g_acc5, DD / 8);
    __threadfence();
    __shared__ unsigned s_old;
    __syncthreads();
    if (threadIdx.x == 0) s_old = atomicAdd(&g_tile_ctr[blockIdx.x], 1u);
    __syncthreads();
    if (s_old == 7u) {
        __threadfence();
        int n0 = blockIdx.x * 64;
        for (int i = threadIdx.x; i < 64 * 64; i += 256) {
            int r = i >> 6, c = i & 63;
            out[(size_t)r * DD + n0 + c] = tanhf(g_acc5[(size_t)r * DD + n0 + c]);
        }
    }
}

// ---------------- fused attention pass: single context read ----------------
// grid (SPLIT, BB), 128 threads. Warp w processes row-pairs {8p+2w, 8p+2w+1};
// register double-buffer (stage-indexed, unroll-2), pairwise online softmax.
__global__ __launch_bounds__(128) void attn_pass(const float* __restrict__ ctx,
                                                 float* __restrict__ attn0,
                                                 float* __restrict__ attn1) {
    const int b = blockIdx.y, sp = blockIdx.x;
    const int tid = threadIdx.x, lane = tid & 31, w = tid >> 5;

    __shared__ __align__(16) float sq[2][4][32][4];   // 4 KB lane-ordered q
    __shared__ float sacc[2][DH];                     // 4 KB
    __shared__ float smx[2][4], ssm[2][4];

    // sq[k][j][l][t] = target[b, (l+32j)*8 + 2t + k]  (= q_k at d=(l+32j)*4+t)
    for (int f = tid; f < 256; f += 128) {
        int k = f >> 7, j = (f >> 5) & 3, l = f & 31;
        const float* g = g_target + (size_t)b * DD + (size_t)(l + 32 * j) * 8 + k;
        float4 v; v.x = g[0]; v.y = g[2]; v.z = g[4]; v.w = g[6];
        *(float4*)&sq[k][j][l][0] = v;
    }
    for (int i = tid; i < 2 * DH; i += 128) (&sacc[0][0])[i] = 0.f;
    __syncthreads();

    const float4* base = (const float4*)(ctx + ((size_t)b * LL + (size_t)sp * LC) * DH);
    float* a0p = attn0 + (size_t)b * LL + sp * LC;
    float* a1p = attn1 + (size_t)b * LL + sp * LC;

    float a0[16], a1[16];
#pragma unroll
    for (int i = 0; i < 16; i++) { a0[i] = 0.f; a1[i] = 0.f; }
    float m0 = -1e30f, m1 = -1e30f, s0 = 0.f, s1 = 0.f;

    // buf[stage][row-in-pair][j]
    float4 buf[2][2][4];
    {
        const float4* rp = base + (size_t)(2 * w) * (DH / 4);
#pragma unroll
        for (int j = 0; j < 4; j++) {
            buf[0][0][j] = rp[lane + 32 * j];
            buf[0][1][j] = rp[128 + lane + 32 * j];
        }
    }

#pragma unroll 2
    for (int p = 0; p < NP; p++) {
        const int st = p & 1;
        if (p + 1 < NP) {
            const float4* rp = base + (size_t)(8 * (p + 1) + 2 * w) * (DH / 4);
#pragma unroll
            for (int j = 0; j < 4; j++) {
                buf[st ^ 1][0][j] = rp[lane + 32 * j];
                buf[st ^ 1][1][j] = rp[128 + lane + 32 * j];
            }
        }

        // 4 interleaved dot products (rows A,B x queries 0,1)
        float dA0 = 0.f, dA1 = 0.f, dB0 = 0.f, dB1 = 0.f;
#pragma unroll
        for (int j = 0; j < 4; j++) {
            float4 q0v = *(const float4*)&sq[0][j][lane][0];
            float4 q1v = *(const float4*)&sq[1][j][lane][0];
            float4 va = buf[st][0][j], vb = buf[st][1][j];
            dA0 = fmaf(va.x, q0v.x, dA0); dA0 = fmaf(va.y, q0v.y, dA0);
            dA0 = fmaf(va.z, q0v.z, dA0); dA0 = fmaf(va.w, q0v.w, dA0);
            dA1 = fmaf(va.x, q1v.x, dA1); dA1 = fmaf(va.y, q1v.y, dA1);
            dA1 = fmaf(va.z, q1v.z, dA1); dA1 = fmaf(va.w, q1v.w, dA1);
            dB0 = fmaf(vb.x, q0v.x, dB0); dB0 = fmaf(vb.y, q0v.y, dB0);
            dB0 = fmaf(vb.z, q0v.z, dB0); dB0 = fmaf(vb.w, q0v.w, dB0);
            dB1 = fmaf(vb.x, q1v.x, dB1); dB1 = fmaf(vb.y, q1v.y, dB1);
            dB1 = fmaf(vb.z, q1v.z, dB1); dB1 = fmaf(vb.w, q1v.w, dB1);
        }
#pragma unroll
        for (int o = 16; o; o >>= 1) {
            dA0 += __shfl_xor_sync(0xffffffffu, dA0, o);
            dA1 += __shfl_xor_sync(0xffffffffu, dA1, o);
            dB0 += __shfl_xor_sync(0xffffffffu, dB0, o);
            dB1 += __shfl_xor_sync(0xffffffffu, dB1, o);
        }
        int r = 8 * p + 2 * w;
        if (lane == 0) {
            a0p[r] = dA0; a0p[r + 1] = dB0;   // raw logits; normalized later
            a1p[r] = dA1; a1p[r + 1] = dB1;
        }
        // pairwise online softmax. r==1 exactly when max didn't move (exp(0)=1),
        // so the rescale loop is warp-uniformly skipped in most iterations.
        float n0 = fmaxf(m0, fmaxf(dA0, dB0));
        float n1 = fmaxf(m1, fmaxf(dA1, dB1));
        float r0 = __expf(m0 - n0), r1 = __expf(m1 - n1);
        float eA0 = __expf(dA0 - n0), eB0 = __expf(dB0 - n0);
        float eA1 = __expf(dA1 - n1), eB1 = __expf(dB1 - n1);
        s0 = s0 * r0 + eA0 + eB0; m0 = n0;
        s1 = s1 * r1 + eA1 + eB1; m1 = n1;
        if (r0 != 1.f || r1 != 1.f) {
#pragma unroll
            for (int i = 0; i < 16; i++) { a0[i] *= r0; a1[i] *= r1; }
        }
#pragma unroll
        for (int j = 0; j < 4; j++) {
            float4 va = buf[st][0][j], vb = buf[st][1][j];
            a0[4 * j + 0] = fmaf(eB0, vb.x, fmaf(eA0, va.x, a0[4 * j + 0]));
            a0[4 * j + 1] = fmaf(eB0, vb.y, fmaf(eA0, va.y, a0[4 * j + 1]));
            a0[4 * j + 2] = fmaf(eB0, vb.z, fmaf(eA0, va.z, a0[4 * j + 2]));
            a0[4 * j + 3] = fmaf(eB0, vb.w, fmaf(eA0, va.w, a0[4 * j + 3]));
            a1[4 * j + 0] = fmaf(eB1, vb.x, fmaf(eA1, va.x, a1[4 * j + 0]));
            a1[4 * j + 1] = fmaf(eB1, vb.y, fmaf(eA1, va.y, a1[4 * j + 1]));
            a1[4 * j + 2] = fmaf(eB1, vb.z, fmaf(eA1, va.z, a1[4 * j + 2]));
            a1[4 * j + 3] = fmaf(eB1, vb.w, fmaf(eA1, va.w, a1[4 * j + 3]));
        }
    }

    // ---- combine 4 warps within the CTA ----
    if (lane == 0) {
        smx[0][w] = m0; smx[1][w] = m1;
        ssm[0][w] = s0; ssm[1][w] = s1;
    }
    __syncthreads();
    float M0 = fmaxf(fmaxf(smx[0][0], smx[0][1]), fmaxf(smx[0][2], smx[0][3]));
    float M1 = fmaxf(fmaxf(smx[1][0], smx[1][1]), fmaxf(smx[1][2], smx[1][3]));
    float f0 = __expf(m0 - M0);
    float f1 = __expf(m1 - M1);
#pragma unroll
    for (int j = 0; j < 4; j++)
#pragma unroll
        for (int t = 0; t < 4; t++) {
            int d = (lane + 32 * j) * 4 + t;
            atomicAdd(&sacc[0][d], a0[4 * j + t] * f0);
            atomicAdd(&sacc[1][d], a1[4 * j + t] * f1);
        }
    __syncthreads();

    int idx0 = (b * 2 + 0) * SPLIT + sp;
    int idx1 = (b * 2 + 1) * SPLIT + sp;
    if (tid == 0) {
        float S0 = 0.f, S1 = 0.f;
#pragma unroll
        for (int ww = 0; ww < 4; ww++) {
            S0 += ssm[0][ww] * __expf(smx[0][ww] - M0);
            S1 += ssm[1][ww] * __expf(smx[1][ww] - M1);
        }
        g_pm[idx0] = M0; g_ps[idx0] = S0;
        g_pm[idx1] = M1; g_ps[idx1] = S1;
    }
    for (int i = tid; i < DH; i += 128) {
        g_pacc[(size_t)idx0 * DH + i] = sacc[0][i];
        g_pacc[(size_t)idx1 * DH + i] = sacc[1][i];
    }
}

// ---------------- combine SPLIT partials + normalize attn (fused) ----------------
__global__ __launch_bounds__(256) void combine_norm(float* __restrict__ out) {
    int bk = blockIdx.x;                 // 0..127 = b*2+k
    int b = bk >> 1, k = bk & 1;
    __shared__ float wgt[SPLIT];
    __shared__ float sM, sInv;
    if (threadIdx.x == 0) {
        float M = -1e30f;
#pragma unroll
        for (int sp = 0; sp < SPLIT; sp++) M = fmaxf(M, g_pm[bk * SPLIT + sp]);
        float S = 0.f;
#pragma unroll
        for (int sp = 0; sp < SPLIT; sp++) {
            float wv = __expf(g_pm[bk * SPLIT + sp] - M);
            wgt[sp] = wv;
            S += g_ps[bk * SPLIT + sp] * wv;
        }
        sM = M; sInv = 1.0f / S;
    }
    __syncthreads();
    float M = sM, inv = sInv;
    for (int d = threadIdx.x; d < DH; d += 256) {
        float acc = 0.f;
#pragma unroll
        for (int sp = 0; sp < SPLIT; sp++)
            acc += g_pacc[(size_t)(bk * SPLIT + sp) * DH + d] * wgt[sp];
        g_wctx[(size_t)b * DD + k * DH + d] = acc * inv;
    }
    float* attn = out + BB * DD + (size_t)k * BB * LL + (size_t)b * LL;
    for (int i = threadIdx.x; i < LL; i += 256)
        attn[i] = __expf(attn[i] - M) * inv;
}

// ---------------- launcher ----------------
extern "C" void kernel_launch(void* const* d_in, const int* in_sizes, int n_in,
                              void* d_out, int out_size) {
    const float* input   = (const float*)d_in[0]; // [64,1024]
    const float* context = (const float*)d_in[1]; // [64,2048,512]
    const float* W_in    = (const float*)d_in[2]; // [1024,1024]
    const float* W_out   = (const float*)d_in[3]; // [1024,2048]
    float* out = (float*)d_out;                   // [ctxOut | attn0 | attn1]

    prep_kernel<<<(BB * DD + 255) / 256, 256>>>();
    gemm_dual<<<dim3(DD / 64, 8, 2), 256>>>(input, W_in, W_out);
    attn_pass<<<dim3(SPLIT, BB), 128>>>(context, out + BB * DD, out + BB * DD + BB * LL);
    combine_norm<<<BB * 2, 256>>>(out);
    gemm_out_b<<<dim3(DD / 64, 8), 256>>>(W_out, out);
}